// round 1
// baseline (speedup 1.0000x reference)
#include <cuda_runtime.h>

#define BATCHN 8
#define TT 2048
#define EE 1024
#define DD 128
#define MTOT (BATCHN*TT)

// Scratch for Q,K,V projections (8 MB each) — __device__ globals per allocation rules.
__device__ float g_q[MTOT*DD];
__device__ float g_k[MTOT*DD];
__device__ float g_v[MTOT*DD];

// ---------------------------------------------------------------------------
// QKV projection: out = X @ W.  X [16384,1024] row-major, W [1024,128] row-major.
// Tile 128x128, BK=8, 256 threads, 8x8 per-thread micro-tile.
// gridDim = (128, 3): y selects Wq/Wk/Wv.
// ---------------------------------------------------------------------------
__global__ __launch_bounds__(256) void qkv_gemm_kernel(
    const float* __restrict__ X, const float* __restrict__ Wq,
    const float* __restrict__ Wk, const float* __restrict__ Wv) {
  __shared__ float Xs[8][128];   // [k][m] (transposed for contiguous m loads)
  __shared__ float Ws[8][128];   // [k][n]
  const int which = blockIdx.y;
  const float* __restrict__ W = (which == 0) ? Wq : (which == 1) ? Wk : Wv;
  float* __restrict__ outp = (which == 0) ? g_q : (which == 1) ? g_k : g_v;

  const int m0 = blockIdx.x * 128;
  const int tid = threadIdx.x;
  const int tm = tid >> 4;        // 0..15 -> rows tm*8..tm*8+7
  const int tn = tid & 15;        // 0..15 -> cols tn*8..tn*8+7
  const int xm = tid >> 1;        // 0..127 row for X load
  const int xk = (tid & 1) << 2;  // 0 or 4
  const int wk = tid >> 5;        // 0..7
  const int wn = (tid & 31) << 2; // 0..124

  float acc[8][8];
#pragma unroll
  for (int i = 0; i < 8; i++)
#pragma unroll
    for (int j = 0; j < 8; j++) acc[i][j] = 0.f;

  for (int k0 = 0; k0 < EE; k0 += 8) {
    float4 xv = *(const float4*)&X[(size_t)(m0 + xm) * EE + k0 + xk];
    float4 wv = *(const float4*)&W[(size_t)(k0 + wk) * DD + wn];
    __syncthreads();  // previous tile's compute done before overwrite
    Xs[xk + 0][xm] = xv.x;
    Xs[xk + 1][xm] = xv.y;
    Xs[xk + 2][xm] = xv.z;
    Xs[xk + 3][xm] = xv.w;
    *(float4*)&Ws[wk][wn] = wv;
    __syncthreads();
#pragma unroll
    for (int kk = 0; kk < 8; kk++) {
      float a[8], b[8];
      *(float4*)&a[0] = *(const float4*)&Xs[kk][tm * 8];
      *(float4*)&a[4] = *(const float4*)&Xs[kk][tm * 8 + 4];
      *(float4*)&b[0] = *(const float4*)&Ws[kk][tn * 8];
      *(float4*)&b[4] = *(const float4*)&Ws[kk][tn * 8 + 4];
#pragma unroll
      for (int i = 0; i < 8; i++)
#pragma unroll
        for (int j = 0; j < 8; j++) acc[i][j] += a[i] * b[j];
    }
  }

#pragma unroll
  for (int i = 0; i < 8; i++) {
    size_t row = (size_t)(m0 + tm * 8 + i);
    float4 o0 = make_float4(acc[i][0], acc[i][1], acc[i][2], acc[i][3]);
    float4 o1 = make_float4(acc[i][4], acc[i][5], acc[i][6], acc[i][7]);
    *(float4*)&outp[row * DD + tn * 8] = o0;
    *(float4*)&outp[row * DD + tn * 8 + 4] = o1;
  }
}

// ---------------------------------------------------------------------------
// Causal flash attention (fp32, online softmax).
// BQ=64 query rows per block-pass, BK=32 key rows per tile, D=128.
// Each CTA processes query blocks qb=blockIdx.x and 31-blockIdx.x (load balance:
// 2*(qb+1) + 2*(32-qb) = 66 key tiles per CTA, uniform).  grid = (16, 8).
// ---------------------------------------------------------------------------
#define BQ 64
#define BK 32
#define SQ 132   // Qs stride (float4-aligned, conflict-free)
#define SKS 132  // Ks stride
#define SV 128   // Vs stride
#define SSS 33   // Ss stride

#define OFF_Q 0
#define OFF_K (OFF_Q + BQ * SQ)        // 8448
#define OFF_V (OFF_K + BK * SKS)       // 12672
#define OFF_S (OFF_V + BK * SV)        // 16768
#define OFF_M (OFF_S + BQ * SSS)       // 18880
#define OFF_L (OFF_M + BQ)
#define OFF_A (OFF_L + BQ)
#define SMEM_FLOATS (OFF_A + BQ)       // 19072 floats = 76288 bytes

__global__ __launch_bounds__(256) void attn_kernel(float* __restrict__ out) {
  extern __shared__ float sm_[];
  float* Qs = sm_ + OFF_Q;
  float* Ks = sm_ + OFF_K;
  float* Vs = sm_ + OFF_V;
  float* Ss = sm_ + OFF_S;
  float* mrow = sm_ + OFF_M;
  float* lrow = sm_ + OFF_L;
  float* arow = sm_ + OFF_A;

  const int b = blockIdx.y;
  const int tid = threadIdx.x;
  const float* __restrict__ qp = g_q + (size_t)b * TT * DD;
  const float* __restrict__ kp = g_k + (size_t)b * TT * DD;
  const float* __restrict__ vp = g_v + (size_t)b * TT * DD;
  const float scale = 0.08838834764831845f;  // 1/sqrt(128)

  const int rm = tid >> 5, rn = tid & 31;    // PV/output layout
  const int smi = tid >> 3, snj = tid & 7;   // S layout

  for (int pass = 0; pass < 2; pass++) {
    const int qblk = pass ? (TT / BQ - 1 - (int)blockIdx.x) : (int)blockIdx.x;
    __syncthreads();  // previous pass readers (lrow, tiles) done

    // Load Q tile (pre-scaled): 64x128 floats
#pragma unroll
    for (int it = 0; it < 8; it++) {
      int idx = tid + it * 256;
      int r = idx >> 5;
      int d4 = (idx & 31) << 2;
      float4 v = *(const float4*)&qp[(size_t)(qblk * BQ + r) * DD + d4];
      Qs[r * SQ + d4 + 0] = v.x * scale;
      Qs[r * SQ + d4 + 1] = v.y * scale;
      Qs[r * SQ + d4 + 2] = v.z * scale;
      Qs[r * SQ + d4 + 3] = v.w * scale;
    }
    if (tid < BQ) {
      mrow[tid] = -1e30f;
      lrow[tid] = 0.f;
    }

    float o[8][4];
#pragma unroll
    for (int i = 0; i < 8; i++)
#pragma unroll
      for (int j = 0; j < 4; j++) o[i][j] = 0.f;

    const int nkt = 2 * (qblk + 1);
    for (int kt = 0; kt < nkt; kt++) {
      // Load K,V tiles: 32x128 each
#pragma unroll
      for (int it = 0; it < 4; it++) {
        int idx = tid + it * 256;
        int r = idx >> 5;
        int d4 = (idx & 31) << 2;
        float4 kv = *(const float4*)&kp[(size_t)(kt * BK + r) * DD + d4];
        Ks[r * SKS + d4 + 0] = kv.x;
        Ks[r * SKS + d4 + 1] = kv.y;
        Ks[r * SKS + d4 + 2] = kv.z;
        Ks[r * SKS + d4 + 3] = kv.w;
        float4 vv = *(const float4*)&vp[(size_t)(kt * BK + r) * DD + d4];
        *(float4*)&Vs[r * SV + d4] = vv;
      }
      __syncthreads();

      // S = Q K^T  (each thread: 2 rows x 4 cols)
      float s[2][4];
#pragma unroll
      for (int i = 0; i < 2; i++)
#pragma unroll
        for (int j = 0; j < 4; j++) s[i][j] = 0.f;

#pragma unroll 8
      for (int d = 0; d < DD; d += 4) {
        float4 q0 = *(const float4*)&Qs[smi * SQ + d];
        float4 q1 = *(const float4*)&Qs[(smi + 32) * SQ + d];
        float4 k0 = *(const float4*)&Ks[snj * SKS + d];
        float4 k1 = *(const float4*)&Ks[(snj + 8) * SKS + d];
        float4 k2 = *(const float4*)&Ks[(snj + 16) * SKS + d];
        float4 k3 = *(const float4*)&Ks[(snj + 24) * SKS + d];
        s[0][0] += q0.x * k0.x + q0.y * k0.y + q0.z * k0.z + q0.w * k0.w;
        s[0][1] += q0.x * k1.x + q0.y * k1.y + q0.z * k1.z + q0.w * k1.w;
        s[0][2] += q0.x * k2.x + q0.y * k2.y + q0.z * k2.z + q0.w * k2.w;
        s[0][3] += q0.x * k3.x + q0.y * k3.y + q0.z * k3.z + q0.w * k3.w;
        s[1][0] += q1.x * k0.x + q1.y * k0.y + q1.z * k0.z + q1.w * k0.w;
        s[1][1] += q1.x * k1.x + q1.y * k1.y + q1.z * k1.z + q1.w * k1.w;
        s[1][2] += q1.x * k2.x + q1.y * k2.y + q1.z * k2.z + q1.w * k2.w;
        s[1][3] += q1.x * k3.x + q1.y * k3.y + q1.z * k3.z + q1.w * k3.w;
      }

      // Causal mask (only diagonal tiles need it)
      if (kt >= 2 * qblk) {
#pragma unroll
        for (int i = 0; i < 2; i++)
#pragma unroll
          for (int j = 0; j < 4; j++) {
            int qg = qblk * BQ + smi + 32 * i;
            int kg = kt * BK + snj + 8 * j;
            if (kg > qg) s[i][j] = -1e30f;
          }
      }
#pragma unroll
      for (int i = 0; i < 2; i++)
#pragma unroll
        for (int j = 0; j < 4; j++)
          Ss[(smi + 32 * i) * SSS + snj + 8 * j] = s[i][j];
      __syncthreads();

      // Online softmax stats: one thread per query row
      if (tid < BQ) {
        float mo = mrow[tid];
        float mn = mo;
#pragma unroll
        for (int c = 0; c < BK; c++) mn = fmaxf(mn, Ss[tid * SSS + c]);
        float al = __expf(mo - mn);
        float sum = 0.f;
#pragma unroll
        for (int c = 0; c < BK; c++) {
          float p = __expf(Ss[tid * SSS + c] - mn);
          Ss[tid * SSS + c] = p;
          sum += p;
        }
        lrow[tid] = lrow[tid] * al + sum;
        mrow[tid] = mn;
        arow[tid] = al;
      }
      __syncthreads();

      // Rescale O and accumulate O += P @ V (each thread: 8 rows x 4 cols)
      float al[8];
#pragma unroll
      for (int i = 0; i < 8; i++) al[i] = arow[rm + 8 * i];
#pragma unroll
      for (int i = 0; i < 8; i++)
#pragma unroll
        for (int j = 0; j < 4; j++) o[i][j] *= al[i];

#pragma unroll 4
      for (int k = 0; k < BK; k++) {
        float4 v = *(const float4*)&Vs[k * SV + rn * 4];
#pragma unroll
        for (int i = 0; i < 8; i++) {
          float p = Ss[(rm + 8 * i) * SSS + k];
          o[i][0] += p * v.x;
          o[i][1] += p * v.y;
          o[i][2] += p * v.z;
          o[i][3] += p * v.w;
        }
      }
      __syncthreads();  // tiles free for next kt
    }

    // Output: divide by row sum; float4 coalesced stores
#pragma unroll
    for (int i = 0; i < 8; i++) {
      int r = rm + 8 * i;
      float inv = 1.f / lrow[r];
      size_t base = ((size_t)b * TT + (size_t)qblk * BQ + r) * DD;
      float4 ov = make_float4(o[i][0] * inv, o[i][1] * inv, o[i][2] * inv,
                              o[i][3] * inv);
      *(float4*)&out[base + rn * 4] = ov;
    }
  }
}

// ---------------------------------------------------------------------------
extern "C" void kernel_launch(void* const* d_in, const int* in_sizes, int n_in,
                              void* d_out, int out_size) {
  const float* X = (const float*)d_in[0];
  const float* Wq = (const float*)d_in[1];
  const float* Wk = (const float*)d_in[2];
  const float* Wv = (const float*)d_in[3];
  float* out = (float*)d_out;

  qkv_gemm_kernel<<<dim3(128, 3), 256>>>(X, Wq, Wk, Wv);

  const int smem_bytes = SMEM_FLOATS * (int)sizeof(float);
  cudaFuncSetAttribute((const void*)attn_kernel,
                       cudaFuncAttributeMaxDynamicSharedMemorySize, smem_bytes);
  attn_kernel<<<dim3(16, BATCHN), 256, smem_bytes>>>(out);
}